// round 1
// baseline (speedup 1.0000x reference)
#include <cuda_runtime.h>

#define N_NODES 50000
#define D 128
#define SPAD 132   // padded row stride for transposed W in smem (16B aligned)

// Scratch (device globals: no allocation allowed in kernel_launch)
__device__ float g_S[N_NODES * D];   // sum_e e*feat[src] per dst node
__device__ float g_c[N_NODES];      // sum_e e per dst node
__device__ float g_deg[N_NODES];    // edge count per dst node

// ---------------------------------------------------------------------------
// Zero the scratch accumulators.
// ---------------------------------------------------------------------------
__global__ void zero_kernel() {
    int tid = blockIdx.x * blockDim.x + threadIdx.x;
    int stride = gridDim.x * blockDim.x;
    float4* S4 = reinterpret_cast<float4*>(g_S);
    const int total4 = N_NODES * D / 4;
    float4 z = make_float4(0.f, 0.f, 0.f, 0.f);
    for (int i = tid; i < total4; i += stride) S4[i] = z;
    for (int i = tid; i < N_NODES; i += stride) { g_c[i] = 0.f; g_deg[i] = 0.f; }
}

// ---------------------------------------------------------------------------
// Edge scatter: one warp per edge. Lane l handles 4 contiguous floats.
// S[dst] += e * feat[src]  (red.global.add.v4.f32, one 16B op per lane)
// ---------------------------------------------------------------------------
__global__ void scatter_kernel(const float* __restrict__ feat,
                               const int* __restrict__ esrc,
                               const int* __restrict__ edst,
                               const float* __restrict__ ee, int E) {
    int gw = (blockIdx.x * blockDim.x + threadIdx.x) >> 5;
    int lane = threadIdx.x & 31;
    if (gw >= E) return;
    int s = esrc[gw];
    int d = edst[gw];
    float ev = ee[gw];
    float4 v = reinterpret_cast<const float4*>(feat + (size_t)s * D)[lane];
    v.x *= ev; v.y *= ev; v.z *= ev; v.w *= ev;
    float* p = g_S + (size_t)d * D + lane * 4;
    asm volatile("red.global.add.v4.f32 [%0], {%1,%2,%3,%4};"
                 :: "l"(p), "f"(v.x), "f"(v.y), "f"(v.z), "f"(v.w) : "memory");
    if (lane == 0) {
        atomicAdd(&g_c[d], ev);
        atomicAdd(&g_deg[d], 1.0f);
    }
}

// ---------------------------------------------------------------------------
// Per-node matvec + epilogue. Persistent blocks; W^T cached in smem once per
// block. Each warp handles 4 nodes; each lane owns 4 output dims.
// Inner loop per k: 1 LDS.128 (W^T) + 4 broadcast LDS (S rows) + 16 FFMA.
// out[n] = relu((W @ S[n] + b*c[n]) / max(deg[n],1)) + alpha[n]*feat[n]
// ---------------------------------------------------------------------------
__global__ void __launch_bounds__(256, 2) gemm_finalize_kernel(
    const float* __restrict__ feat, const float* __restrict__ alpha,
    const float* __restrict__ W, const float* __restrict__ b,
    float* __restrict__ out) {
    extern __shared__ float sm[];
    float* Ws = sm;               // [D][SPAD]  Ws[k*SPAD + i] = W[i][k]
    float* Ss = sm + D * SPAD;    // [8 warps][4 nodes][D]

    int tid = threadIdx.x, warp = tid >> 5, lane = tid & 31;

    // Load W transposed into smem (coalesced global reads)
    for (int idx = tid; idx < D * D; idx += blockDim.x) {
        int i = idx >> 7;          // output dim
        int k = idx & (D - 1);     // input dim
        Ws[k * SPAD + i] = W[idx];
    }
    __syncthreads();

    const int oi = lane * 4;       // this lane's 4 output dims
    float4 bb = *reinterpret_cast<const float4*>(b + oi);
    float* ss = Ss + warp * (4 * D);

    const int numTiles = (N_NODES + 31) / 32;   // 32 nodes per block-tile
    for (int tile = blockIdx.x; tile < numTiles; tile += gridDim.x) {
        int n0 = tile * 32 + warp * 4;

        // stage 4 S rows into this warp's smem slab
        #pragma unroll
        for (int r = 0; r < 4; r++) {
            int n = n0 + r;
            float4 v = (n < N_NODES)
                ? reinterpret_cast<const float4*>(g_S + (size_t)n * D)[lane]
                : make_float4(0.f, 0.f, 0.f, 0.f);
            reinterpret_cast<float4*>(ss + r * D)[lane] = v;
        }
        __syncwarp();

        float acc[4][4];
        #pragma unroll
        for (int r = 0; r < 4; r++)
            #pragma unroll
            for (int j = 0; j < 4; j++) acc[r][j] = 0.f;

        #pragma unroll 4
        for (int k = 0; k < D; k++) {
            float4 w = *reinterpret_cast<const float4*>(&Ws[k * SPAD + oi]);
            #pragma unroll
            for (int r = 0; r < 4; r++) {
                float sv = ss[r * D + k];   // broadcast
                acc[r][0] += w.x * sv;
                acc[r][1] += w.y * sv;
                acc[r][2] += w.z * sv;
                acc[r][3] += w.w * sv;
            }
        }

        #pragma unroll
        for (int r = 0; r < 4; r++) {
            int n = n0 + r;
            if (n < N_NODES) {
                float cv = g_c[n];
                float inv = 1.0f / fmaxf(g_deg[n], 1.0f);
                float a = alpha[n];
                float4 f = reinterpret_cast<const float4*>(feat + (size_t)n * D)[lane];
                float4 o;
                o.x = fmaxf((acc[r][0] + bb.x * cv) * inv, 0.f) + a * f.x;
                o.y = fmaxf((acc[r][1] + bb.y * cv) * inv, 0.f) + a * f.y;
                o.z = fmaxf((acc[r][2] + bb.z * cv) * inv, 0.f) + a * f.z;
                o.w = fmaxf((acc[r][3] + bb.w * cv) * inv, 0.f) + a * f.w;
                reinterpret_cast<float4*>(out + (size_t)n * D)[lane] = o;
            }
        }
        __syncwarp();
    }
}

extern "C" void kernel_launch(void* const* d_in, const int* in_sizes, int n_in,
                              void* d_out, int out_size) {
    const float* feat  = (const float*)d_in[0];
    const float* alpha = (const float*)d_in[1];
    const int*   esrc  = (const int*)d_in[2];
    const int*   edst  = (const int*)d_in[3];
    const float* ee    = (const float*)d_in[4];
    const float* W     = (const float*)d_in[5];
    const float* b     = (const float*)d_in[6];
    float* out = (float*)d_out;
    const int E = in_sizes[2];

    zero_kernel<<<1024, 256>>>();

    int scatter_blocks = (E * 32 + 255) / 256;   // one warp per edge
    scatter_kernel<<<scatter_blocks, 256>>>(feat, esrc, edst, ee, E);

    const int smem_bytes = (D * SPAD + 8 * 4 * D) * (int)sizeof(float);
    cudaFuncSetAttribute(gemm_finalize_kernel,
                         cudaFuncAttributeMaxDynamicSharedMemorySize, smem_bytes);
    gemm_finalize_kernel<<<296, 256, smem_bytes>>>(feat, alpha, W, b, out);
}